// round 6
// baseline (speedup 1.0000x reference)
#include <cuda_runtime.h>
#include <cuda_bf16.h>
#include <cstdint>

#define D 128
#define MAXN 100000
#define MAXE 600000
#define SCAN_NB ((MAXN + 255) / 256)   // 391

// Scratch (device globals; no allocs allowed)
__device__ float  g_A[(size_t)MAXN * D];   // 51.2 MB
__device__ int    g_count[MAXN];           // self-cleared by gather each run
__device__ int    g_offs[MAXN];
__device__ int    g_bsum[SCAN_NB + 1];
__device__ float2 g_meta[MAXE];            // (.x = src id bits, .y = w)

// ---------------------------------------------------------------------------
// hist: counts per dst (g_count enters zeroed: BSS init / gather self-clear)
// ---------------------------------------------------------------------------
__global__ void hist_kernel(const int* __restrict__ ei, int E) {
    int e = blockIdx.x * blockDim.x + threadIdx.x;
    if (e < E) atomicAdd(&g_count[ei[E + e]], 1);
}

// scan1: per-256-block exclusive scan (shuffles); block totals to g_bsum
__global__ void scan1_kernel(int N) {
    __shared__ int ws[8];
    int tid = threadIdx.x;
    int lane = tid & 31, wrp = tid >> 5;
    int i = blockIdx.x * 256 + tid;
    int c = (i < N) ? g_count[i] : 0;
    int v = c;
#pragma unroll
    for (int o = 1; o < 32; o <<= 1) {
        int t = __shfl_up_sync(0xffffffffu, v, o);
        if (lane >= o) v += t;
    }
    if (lane == 31) ws[wrp] = v;
    __syncthreads();
    if (wrp == 0) {
        int s = (lane < 8) ? ws[lane] : 0;
#pragma unroll
        for (int o = 1; o < 8; o <<= 1) {
            int t = __shfl_up_sync(0xffffffffu, s, o);
            if (lane >= o) s += t;
        }
        if (lane < 8) ws[lane] = s;
    }
    __syncthreads();
    int incl = v + ((wrp > 0) ? ws[wrp - 1] : 0);
    if (i < N) g_offs[i] = incl - c;
    if (tid == 255) g_bsum[blockIdx.x] = incl;
}

// scan23: each block redundantly reduces g_bsum[0..b) and adds to its offs
__global__ void scan23_kernel(int N) {
    __shared__ int ssum[8];
    int b = blockIdx.x;
    int tid = threadIdx.x;
    int s = 0;
    for (int j = tid; j < b; j += 256) s += g_bsum[j];
#pragma unroll
    for (int o = 16; o; o >>= 1) s += __shfl_down_sync(0xffffffffu, s, o);
    if ((tid & 31) == 0) ssum[tid >> 5] = s;
    __syncthreads();
    if (tid == 0) {
        int t = 0;
#pragma unroll
        for (int u = 0; u < 8; ++u) t += ssum[u];
        ssum[0] = t;
    }
    __syncthreads();
    int S = ssum[0];
    int i = b * 256 + tid;
    if (i < N) g_offs[i] += S;
}

// permute: write (src, w) into dst-sorted position; advances g_offs in place
__global__ void permute_kernel(const int* __restrict__ ei,
                               const float* __restrict__ ew, int E) {
    int e = blockIdx.x * blockDim.x + threadIdx.x;
    if (e < E) {
        int dst = ei[E + e];
        int src = ei[e];
        float w = ew[e];
        int pos = atomicAdd(&g_offs[dst], 1);
        g_meta[pos] = make_float2(__int_as_float(src), w);
    }
}

// ---------------------------------------------------------------------------
// Gather: one warp per dst node; base = offs_end - deg. Self-clears g_count.
// ---------------------------------------------------------------------------
__global__ __launch_bounds__(256) void gather_kernel(
    const float* __restrict__ src_x, int N) {
    int w = (blockIdx.x * 256 + threadIdx.x) >> 5;
    int lane = threadIdx.x & 31;
    if (w >= N) return;
    int deg = g_count[w];
    int base = g_offs[w] - deg;
    if (lane == 0) g_count[w] = 0;     // restore invariant for next run
    float4 acc = make_float4(0.f, 0.f, 0.f, 0.f);

    for (int c0 = 0; c0 < deg; c0 += 32) {
        int cn = min(deg - c0, 32);
        float2 mv = make_float2(0.f, 0.f);
        if (lane < cn) mv = __ldg(&g_meta[base + c0 + lane]);
        for (int j = 0; j < cn; j += 4) {
            float4 x[4];
            float wv[4];
#pragma unroll
            for (int u = 0; u < 4; ++u) {
                int idx = j + u;
                int su = __shfl_sync(0xffffffffu, __float_as_int(mv.x), idx & 31);
                float wu = __shfl_sync(0xffffffffu, mv.y, idx & 31);
                bool valid = idx < cn;
                wv[u] = valid ? wu : 0.f;
                if (valid)
                    x[u] = __ldg((const float4*)(src_x + (size_t)su * D) + lane);
                else
                    x[u] = make_float4(0.f, 0.f, 0.f, 0.f);
            }
#pragma unroll
            for (int u = 0; u < 4; ++u) {
                acc.x += wv[u] * x[u].x;
                acc.y += wv[u] * x[u].y;
                acc.z += wv[u] * x[u].z;
                acc.w += wv[u] * x[u].w;
            }
        }
    }
    ((float4*)(g_A + (size_t)w * D))[lane] = acc;
}

// ---------------------------------------------------------------------------
// Fused dual GEMM + leaky_relu, cp.async double-buffered.
//   out = leaky_relu( (dst_x + A) @ Wi^T + (dst_x * A) @ Wn^T )
// BM=64, BK=8, 16 k-tiles. Raw fp32 tiles in smem (pad 12 -> conflict-free);
// tf32 convert + u/v elementwise math at fragment-load time (d/a shared by
// both phases). No register staging across mma -> no spills.
// ---------------------------------------------------------------------------
#define KP 12

__device__ __forceinline__ uint32_t f2tf32(float x) {
    uint32_t r;
    asm("cvt.rna.tf32.f32 %0, %1;" : "=r"(r) : "f"(x));
    return r;
}

__device__ __forceinline__ void mma_tf32(float c[4], const uint32_t a[4],
                                         const uint32_t b[2]) {
    asm volatile(
        "mma.sync.aligned.m16n8k8.row.col.f32.tf32.tf32.f32 "
        "{%0,%1,%2,%3},{%4,%5,%6,%7},{%8,%9},{%0,%1,%2,%3};"
        : "+f"(c[0]), "+f"(c[1]), "+f"(c[2]), "+f"(c[3])
        : "r"(a[0]), "r"(a[1]), "r"(a[2]), "r"(a[3]), "r"(b[0]), "r"(b[1]));
}

__device__ __forceinline__ void cp16(uint32_t saddr, const float* g, bool valid) {
    asm volatile("cp.async.cg.shared.global [%0], [%1], 16, %2;"
                 :: "r"(saddr), "l"(g), "r"(valid ? 16 : 0));
}
#define CP_COMMIT() asm volatile("cp.async.commit_group;")
#define CP_WAIT(n)  asm volatile("cp.async.wait_group %0;" :: "n"(n))

__global__ __launch_bounds__(256) void fused_gemm_tc_kernel(
    const float* __restrict__ dstx,
    const float* __restrict__ Wi,
    const float* __restrict__ Wn,
    float* __restrict__ out, int N) {

    __shared__ float d_s[2][64][KP];
    __shared__ float a_s[2][64][KP];
    __shared__ float wi_s[2][128][KP];
    __shared__ float wn_s[2][128][KP];

    const int tid = threadIdx.x;
    const int lane = tid & 31;
    const int wid = tid >> 5;
    const int wm = wid >> 2;     // 0..1 : 32-row half
    const int wn = wid & 3;      // 0..3 : 32-col block
    const int grp = lane >> 2;   // 0..7
    const int qid = lane & 3;    // 0..3
    const int row0 = blockIdx.x * 64;

    // fill assignments
    const int fr2 = tid >> 1;          // 0..127
    const int fq = (tid & 1) * 4;      // k offset 0 or 4
    const int da_r = (tid & 127) >> 1; // 0..63 (node row in tile)
    const bool do_d = tid < 128;

    const uint32_t sd = (uint32_t)__cvta_generic_to_shared(
        do_d ? &d_s[0][da_r][fq] : &a_s[0][da_r][fq]);
    const uint32_t swi = (uint32_t)__cvta_generic_to_shared(&wi_s[0][fr2][fq]);
    const uint32_t swn = (uint32_t)__cvta_generic_to_shared(&wn_s[0][fr2][fq]);
    const uint32_t bufstep_da = 64 * KP * 4;
    const uint32_t bufstep_w = 128 * KP * 4;
    const float* da_srcbase = do_d ? dstx : (const float*)g_A;
    const bool da_valid = (row0 + da_r) < N;
    const float* da_src0 = da_srcbase + (size_t)(da_valid ? row0 + da_r : 0) * D + fq;

    float acc[2][4][4];
#pragma unroll
    for (int mt = 0; mt < 2; ++mt)
#pragma unroll
        for (int nt = 0; nt < 4; ++nt)
#pragma unroll
            for (int c = 0; c < 4; ++c) acc[mt][nt][c] = 0.f;

#define FILL(kt, b)                                                   \
    do {                                                              \
        int k0_ = (kt) * 8;                                           \
        cp16(sd + (b) * bufstep_da, da_src0 + k0_, da_valid);         \
        cp16(swi + (b) * bufstep_w, Wi + fr2 * D + k0_ + fq, true);   \
        cp16(swn + (b) * bufstep_w, Wn + fr2 * D + k0_ + fq, true);   \
    } while (0)

    FILL(0, 0); CP_COMMIT();
    FILL(1, 1); CP_COMMIT();

#pragma unroll 4
    for (int kt = 0; kt < 16; ++kt) {
        const int b = kt & 1;
        if (kt < 15) { CP_WAIT(1); } else { CP_WAIT(0); }
        __syncthreads();

        // A-side fragments: load d/a once, build u and v
        uint32_t fu[2][4], fv[2][4];
#pragma unroll
        for (int mt = 0; mt < 2; ++mt) {
            int mr = wm * 32 + mt * 16 + grp;
            float d0 = d_s[b][mr][qid],     a0 = a_s[b][mr][qid];
            float d1 = d_s[b][mr + 8][qid], a1 = a_s[b][mr + 8][qid];
            float d2 = d_s[b][mr][qid + 4], a2 = a_s[b][mr][qid + 4];
            float d3 = d_s[b][mr + 8][qid + 4], a3 = a_s[b][mr + 8][qid + 4];
            fu[mt][0] = f2tf32(d0 + a0); fv[mt][0] = f2tf32(d0 * a0);
            fu[mt][1] = f2tf32(d1 + a1); fv[mt][1] = f2tf32(d1 * a1);
            fu[mt][2] = f2tf32(d2 + a2); fv[mt][2] = f2tf32(d2 * a2);
            fu[mt][3] = f2tf32(d3 + a3); fv[mt][3] = f2tf32(d3 * a3);
        }
        // B-side fragments
        uint32_t bi[4][2], bn[4][2];
#pragma unroll
        for (int nt = 0; nt < 4; ++nt) {
            int nc = wn * 32 + nt * 8 + grp;
            bi[nt][0] = f2tf32(wi_s[b][nc][qid]);
            bi[nt][1] = f2tf32(wi_s[b][nc][qid + 4]);
            bn[nt][0] = f2tf32(wn_s[b][nc][qid]);
            bn[nt][1] = f2tf32(wn_s[b][nc][qid + 4]);
        }
#pragma unroll
        for (int mt = 0; mt < 2; ++mt)
#pragma unroll
            for (int nt = 0; nt < 4; ++nt) {
                mma_tf32(acc[mt][nt], fu[mt], bi[nt]);
                mma_tf32(acc[mt][nt], fv[mt], bn[nt]);
            }
        __syncthreads();
        if (kt < 14) { FILL(kt + 2, b); CP_COMMIT(); }
    }

    // epilogue: leaky_relu + float2 stores
#pragma unroll
    for (int mt = 0; mt < 2; ++mt) {
#pragma unroll
        for (int nt = 0; nt < 4; ++nt) {
            int col = wn * 32 + nt * 8 + qid * 2;
            int r0 = row0 + wm * 32 + mt * 16 + grp;
            int r1 = r0 + 8;
            float x0 = acc[mt][nt][0], x1 = acc[mt][nt][1];
            float x2 = acc[mt][nt][2], x3 = acc[mt][nt][3];
            x0 = x0 > 0.f ? x0 : 0.01f * x0;
            x1 = x1 > 0.f ? x1 : 0.01f * x1;
            x2 = x2 > 0.f ? x2 : 0.01f * x2;
            x3 = x3 > 0.f ? x3 : 0.01f * x3;
            if (r0 < N)
                *(float2*)(out + (size_t)r0 * D + col) = make_float2(x0, x1);
            if (r1 < N)
                *(float2*)(out + (size_t)r1 * D + col) = make_float2(x2, x3);
        }
    }
}

// ---------------------------------------------------------------------------
extern "C" void kernel_launch(void* const* d_in, const int* in_sizes, int n_in,
                              void* d_out, int out_size) {
    const float* src_x = (const float*)d_in[0];
    const float* dst_x = (const float*)d_in[1];
    const int*   ei    = (const int*)d_in[2];    // [2, E]
    const float* ew    = (const float*)d_in[3];  // [E]
    const float* Wi    = (const float*)d_in[4];
    const float* Wn    = (const float*)d_in[5];
    float* out = (float*)d_out;

    int N = in_sizes[0] / D;
    int E = in_sizes[2] / 2;
    int nb = (N + 255) / 256;

    hist_kernel<<<(E + 255) / 256, 256>>>(ei, E);
    scan1_kernel<<<nb, 256>>>(N);
    scan23_kernel<<<nb, 256>>>(N);
    permute_kernel<<<(E + 255) / 256, 256>>>(ei, ew, E);
    gather_kernel<<<(N * 32 + 255) / 256, 256>>>(src_x, N);
    fused_gemm_tc_kernel<<<(N + 63) / 64, 256>>>(dst_x, Wi, Wn, out, N);
}

// round 7
// speedup vs baseline: 1.2215x; 1.2215x over previous
#include <cuda_runtime.h>
#include <cuda_bf16.h>
#include <cstdint>

#define D 128
#define MAXN 100000
#define MAXE 600000
#define SCAN_NB ((MAXN + 255) / 256)   // 391

// Scratch (device globals; no allocs allowed)
__device__ float  g_A[(size_t)MAXN * D];   // 51.2 MB
__device__ int    g_count[MAXN];
__device__ int    g_offs[MAXN];
__device__ int    g_cursor[MAXN];
__device__ int    g_bsum[SCAN_NB + 1];
__device__ float2 g_meta[MAXE];            // (.x = src id bits, .y = w)

// ---------------------------------------------------------------------------
// Counting sort of edges by dst (R3-verbatim stages)
// ---------------------------------------------------------------------------
__global__ void zero_count_kernel(int N) {
    int i = blockIdx.x * blockDim.x + threadIdx.x;
    if (i < N) g_count[i] = 0;
}

__global__ void hist_kernel(const int* __restrict__ ei, int E) {
    int e = blockIdx.x * blockDim.x + threadIdx.x;
    if (e < E) atomicAdd(&g_count[ei[E + e]], 1);
}

__global__ void scan1_kernel(int N) {
    __shared__ int s[256];
    int i = blockIdx.x * 256 + threadIdx.x;
    int c = (i < N) ? g_count[i] : 0;
    s[threadIdx.x] = c;
    __syncthreads();
#pragma unroll
    for (int o = 1; o < 256; o <<= 1) {
        int t = (threadIdx.x >= o) ? s[threadIdx.x - o] : 0;
        __syncthreads();
        s[threadIdx.x] += t;
        __syncthreads();
    }
    if (i < N) g_offs[i] = s[threadIdx.x] - c;
    if (threadIdx.x == 255) g_bsum[blockIdx.x] = s[255];
}

__global__ void scan2_kernel(int nb) {
    __shared__ int s[512];
    int c = (threadIdx.x < nb) ? g_bsum[threadIdx.x] : 0;
    s[threadIdx.x] = c;
    __syncthreads();
#pragma unroll
    for (int o = 1; o < 512; o <<= 1) {
        int t = (threadIdx.x >= o) ? s[threadIdx.x - o] : 0;
        __syncthreads();
        s[threadIdx.x] += t;
        __syncthreads();
    }
    if (threadIdx.x < nb) g_bsum[threadIdx.x] = s[threadIdx.x] - c;  // exclusive
}

__global__ void scan3_kernel(int N) {
    int i = blockIdx.x * 256 + threadIdx.x;
    if (i < N) {
        int v = g_offs[i] + g_bsum[i >> 8];
        g_offs[i] = v;
        g_cursor[i] = v;
    }
}

// permute: write (src, w) directly into dst-sorted position via cursor
__global__ void permute_kernel(const int* __restrict__ ei,
                               const float* __restrict__ ew, int E) {
    int e = blockIdx.x * blockDim.x + threadIdx.x;
    if (e < E) {
        int dst = ei[E + e];
        int src = ei[e];
        float w = ew[e];
        int pos = atomicAdd(&g_cursor[dst], 1);
        g_meta[pos] = make_float2(__int_as_float(src), w);
    }
}

// ---------------------------------------------------------------------------
// Gather: one warp per dst node. 2-hop chain (meta -> row), 8-deep
// back-to-back predicated LDG.128 batches for MLP. g_offs is pristine.
// ---------------------------------------------------------------------------
__global__ __launch_bounds__(256) void gather_kernel(
    const float* __restrict__ src_x, int N) {
    int w = (blockIdx.x * 256 + threadIdx.x) >> 5;
    int lane = threadIdx.x & 31;
    if (w >= N) return;
    int base = g_offs[w];
    int deg = g_count[w];
    float4 acc = make_float4(0.f, 0.f, 0.f, 0.f);

    for (int c0 = 0; c0 < deg; c0 += 32) {
        int cn = min(deg - c0, 32);
        float2 mv = make_float2(0.f, 0.f);
        if (lane < cn) mv = __ldg(&g_meta[base + c0 + lane]);
        for (int j = 0; j < cn; j += 8) {
            float4 x[8];
            float wv[8];
#pragma unroll
            for (int u = 0; u < 8; ++u) {
                int idx = j + u;
                int su = __shfl_sync(0xffffffffu, __float_as_int(mv.x), idx & 31);
                float wu = __shfl_sync(0xffffffffu, mv.y, idx & 31);
                bool valid = idx < cn;
                wv[u] = valid ? wu : 0.f;
                if (valid)
                    x[u] = __ldg((const float4*)(src_x + (size_t)su * D) + lane);
                else
                    x[u] = make_float4(0.f, 0.f, 0.f, 0.f);
            }
#pragma unroll
            for (int u = 0; u < 8; ++u) {
                acc.x += wv[u] * x[u].x;
                acc.y += wv[u] * x[u].y;
                acc.z += wv[u] * x[u].z;
                acc.w += wv[u] * x[u].w;
            }
        }
    }
    ((float4*)(g_A + (size_t)w * D))[lane] = acc;
}

// ---------------------------------------------------------------------------
// Fused dual GEMM + leaky_relu on tensor cores (tf32 mma.sync) — R3 verbatim.
//   out = leaky_relu( (dst_x + A) @ Wi^T + (dst_x * A) @ Wn^T )
// ---------------------------------------------------------------------------
#define SSTR 136

__device__ __forceinline__ uint32_t f2tf32(float x) {
    uint32_t r;
    asm("cvt.rna.tf32.f32 %0, %1;" : "=r"(r) : "f"(x));
    return r;
}

__device__ __forceinline__ void mma_tf32(float c[4], const uint32_t a[4],
                                         const uint32_t b[2]) {
    asm volatile(
        "mma.sync.aligned.m16n8k8.row.col.f32.tf32.tf32.f32 "
        "{%0,%1,%2,%3},{%4,%5,%6,%7},{%8,%9},{%0,%1,%2,%3};"
        : "+f"(c[0]), "+f"(c[1]), "+f"(c[2]), "+f"(c[3])
        : "r"(a[0]), "r"(a[1]), "r"(a[2]), "r"(a[3]), "r"(b[0]), "r"(b[1]));
}

__global__ __launch_bounds__(256) void fused_gemm_tc_kernel(
    const float* __restrict__ dstx,
    const float* __restrict__ Wi,
    const float* __restrict__ Wn,
    float* __restrict__ out, int N) {

    __shared__ uint32_t u_s[16][SSTR];
    __shared__ uint32_t v_s[16][SSTR];
    __shared__ uint32_t wi_s[16][SSTR];
    __shared__ uint32_t wn_s[16][SSTR];

    const int tid = threadIdx.x;
    const int lane = tid & 31;
    const int wid = tid >> 5;
    const int wm = wid >> 2;
    const int wn = wid & 3;
    const int grp = lane >> 2;
    const int qid = lane & 3;
    const int row0 = blockIdx.x * 128;

    const int fm = tid >> 1;
    const int fkq = (tid & 1) * 8;

    float acc[4][4][4];
#pragma unroll
    for (int mt = 0; mt < 4; ++mt)
#pragma unroll
        for (int nt = 0; nt < 4; ++nt)
#pragma unroll
            for (int c = 0; c < 4; ++c) acc[mt][nt][c] = 0.f;

    for (int kt = 0; kt < 8; ++kt) {
        const int k0 = kt * 16;
        {
            int row = row0 + fm;
            float4 d0 = make_float4(0.f, 0.f, 0.f, 0.f), d1 = d0;
            float4 a0 = d0, a1 = d0;
            if (row < N) {
                const float4* dp = (const float4*)(dstx + (size_t)row * D + k0 + fkq);
                const float4* ap = (const float4*)(g_A + (size_t)row * D + k0 + fkq);
                d0 = dp[0]; d1 = dp[1];
                a0 = ap[0]; a1 = ap[1];
            }
            float du[8] = {d0.x, d0.y, d0.z, d0.w, d1.x, d1.y, d1.z, d1.w};
            float au[8] = {a0.x, a0.y, a0.z, a0.w, a1.x, a1.y, a1.z, a1.w};
#pragma unroll
            for (int j = 0; j < 8; ++j) {
                u_s[fkq + j][fm] = f2tf32(du[j] + au[j]);
                v_s[fkq + j][fm] = f2tf32(du[j] * au[j]);
            }
            const float4* wip = (const float4*)(Wi + fm * D + k0 + fkq);
            const float4* wnp = (const float4*)(Wn + fm * D + k0 + fkq);
            float4 wi0 = wip[0], wi1 = wip[1];
            float4 wn0 = wnp[0], wn1 = wnp[1];
            float wif[8] = {wi0.x, wi0.y, wi0.z, wi0.w, wi1.x, wi1.y, wi1.z, wi1.w};
            float wnf[8] = {wn0.x, wn0.y, wn0.z, wn0.w, wn1.x, wn1.y, wn1.z, wn1.w};
#pragma unroll
            for (int j = 0; j < 8; ++j) {
                wi_s[fkq + j][fm] = f2tf32(wif[j]);
                wn_s[fkq + j][fm] = f2tf32(wnf[j]);
            }
        }
        __syncthreads();

#pragma unroll
        for (int ph = 0; ph < 2; ++ph) {
            const uint32_t(*S)[SSTR] = ph ? v_s : u_s;
            const uint32_t(*W)[SSTR] = ph ? wn_s : wi_s;
#pragma unroll
            for (int kk = 0; kk < 16; kk += 8) {
                uint32_t af[4][4];
#pragma unroll
                for (int mt = 0; mt < 4; ++mt) {
                    int mr = wm * 64 + mt * 16 + grp;
                    af[mt][0] = S[kk + qid][mr];
                    af[mt][1] = S[kk + qid][mr + 8];
                    af[mt][2] = S[kk + qid + 4][mr];
                    af[mt][3] = S[kk + qid + 4][mr + 8];
                }
                uint32_t bf[4][2];
#pragma unroll
                for (int nt = 0; nt < 4; ++nt) {
                    int nc = wn * 32 + nt * 8 + grp;
                    bf[nt][0] = W[kk + qid][nc];
                    bf[nt][1] = W[kk + qid + 4][nc];
                }
#pragma unroll
                for (int mt = 0; mt < 4; ++mt)
#pragma unroll
                    for (int nt = 0; nt < 4; ++nt)
                        mma_tf32(acc[mt][nt], af[mt], bf[nt]);
            }
        }
        __syncthreads();
    }

#pragma unroll
    for (int mt = 0; mt < 4; ++mt) {
#pragma unroll
        for (int nt = 0; nt < 4; ++nt) {
            int col = wn * 32 + nt * 8 + qid * 2;
            int r0 = row0 + wm * 64 + mt * 16 + grp;
            int r1 = r0 + 8;
            float x0 = acc[mt][nt][0], x1 = acc[mt][nt][1];
            float x2 = acc[mt][nt][2], x3 = acc[mt][nt][3];
            x0 = x0 > 0.f ? x0 : 0.01f * x0;
            x1 = x1 > 0.f ? x1 : 0.01f * x1;
            x2 = x2 > 0.f ? x2 : 0.01f * x2;
            x3 = x3 > 0.f ? x3 : 0.01f * x3;
            if (r0 < N)
                *(float2*)(out + (size_t)r0 * D + col) = make_float2(x0, x1);
            if (r1 < N)
                *(float2*)(out + (size_t)r1 * D + col) = make_float2(x2, x3);
        }
    }
}

// ---------------------------------------------------------------------------
extern "C" void kernel_launch(void* const* d_in, const int* in_sizes, int n_in,
                              void* d_out, int out_size) {
    const float* src_x = (const float*)d_in[0];
    const float* dst_x = (const float*)d_in[1];
    const int*   ei    = (const int*)d_in[2];    // [2, E]
    const float* ew    = (const float*)d_in[3];  // [E]
    const float* Wi    = (const float*)d_in[4];
    const float* Wn    = (const float*)d_in[5];
    float* out = (float*)d_out;

    int N = in_sizes[0] / D;
    int E = in_sizes[2] / 2;
    int nb = (N + 255) / 256;

    zero_count_kernel<<<nb, 256>>>(N);
    hist_kernel<<<(E + 255) / 256, 256>>>(ei, E);
    scan1_kernel<<<nb, 256>>>(N);
    scan2_kernel<<<1, 512>>>(nb);
    scan3_kernel<<<nb, 256>>>(N);
    permute_kernel<<<(E + 255) / 256, 256>>>(ei, ew, E);
    gather_kernel<<<(N * 32 + 255) / 256, 256>>>(src_x, N);
    fused_gemm_tc_kernel<<<(N + 127) / 128, 256>>>(dst_x, Wi, Wn, out, N);
}

// round 8
// speedup vs baseline: 1.5024x; 1.2300x over previous
#include <cuda_runtime.h>
#include <cuda_fp16.h>
#include <cstdint>

#define D 128
#define MAXN 100000
#define MAXE 600000
#define SCAN_NB ((MAXN + 255) / 256)   // 391

// Scratch (device globals; no allocs allowed)
__device__ float  g_A[(size_t)MAXN * D];     // 51.2 MB
__device__ __half g_srcH[(size_t)MAXN * D];  // 25.6 MB fp16 src cache
__device__ int    g_count[MAXN];
__device__ int    g_offs[MAXN];
__device__ int    g_cursor[MAXN];
__device__ int    g_bsum[SCAN_NB + 1];
__device__ float2 g_meta[MAXE];              // (.x = src id bits, .y = w)

// ---------------------------------------------------------------------------
// Convert src_x -> fp16 cache (one pass; 8 elems/thread)
// ---------------------------------------------------------------------------
__global__ void convert_kernel(const float* __restrict__ src, int n8) {
    int i = blockIdx.x * blockDim.x + threadIdx.x;
    if (i >= n8) return;
    float4 a = __ldg((const float4*)src + 2 * i);
    float4 b = __ldg((const float4*)src + 2 * i + 1);
    __half2 h0 = __floats2half2_rn(a.x, a.y);
    __half2 h1 = __floats2half2_rn(a.z, a.w);
    __half2 h2 = __floats2half2_rn(b.x, b.y);
    __half2 h3 = __floats2half2_rn(b.z, b.w);
    uint4 o;
    o.x = *(uint32_t*)&h0;
    o.y = *(uint32_t*)&h1;
    o.z = *(uint32_t*)&h2;
    o.w = *(uint32_t*)&h3;
    ((uint4*)g_srcH)[i] = o;
}

// ---------------------------------------------------------------------------
// Counting sort of edges by dst (R3-verbatim stages)
// ---------------------------------------------------------------------------
__global__ void zero_count_kernel(int N) {
    int i = blockIdx.x * blockDim.x + threadIdx.x;
    if (i < N) g_count[i] = 0;
}

__global__ void hist_kernel(const int* __restrict__ ei, int E) {
    int e = blockIdx.x * blockDim.x + threadIdx.x;
    if (e < E) atomicAdd(&g_count[ei[E + e]], 1);
}

__global__ void scan1_kernel(int N) {
    __shared__ int s[256];
    int i = blockIdx.x * 256 + threadIdx.x;
    int c = (i < N) ? g_count[i] : 0;
    s[threadIdx.x] = c;
    __syncthreads();
#pragma unroll
    for (int o = 1; o < 256; o <<= 1) {
        int t = (threadIdx.x >= o) ? s[threadIdx.x - o] : 0;
        __syncthreads();
        s[threadIdx.x] += t;
        __syncthreads();
    }
    if (i < N) g_offs[i] = s[threadIdx.x] - c;
    if (threadIdx.x == 255) g_bsum[blockIdx.x] = s[255];
}

__global__ void scan2_kernel(int nb) {
    __shared__ int s[512];
    int c = (threadIdx.x < nb) ? g_bsum[threadIdx.x] : 0;
    s[threadIdx.x] = c;
    __syncthreads();
#pragma unroll
    for (int o = 1; o < 512; o <<= 1) {
        int t = (threadIdx.x >= o) ? s[threadIdx.x - o] : 0;
        __syncthreads();
        s[threadIdx.x] += t;
        __syncthreads();
    }
    if (threadIdx.x < nb) g_bsum[threadIdx.x] = s[threadIdx.x] - c;  // exclusive
}

__global__ void scan3_kernel(int N) {
    int i = blockIdx.x * 256 + threadIdx.x;
    if (i < N) {
        int v = g_offs[i] + g_bsum[i >> 8];
        g_offs[i] = v;
        g_cursor[i] = v;
    }
}

// permute: write (src, w) directly into dst-sorted position via cursor
__global__ void permute_kernel(const int* __restrict__ ei,
                               const float* __restrict__ ew, int E) {
    int e = blockIdx.x * blockDim.x + threadIdx.x;
    if (e < E) {
        int dst = ei[E + e];
        int src = ei[e];
        float w = ew[e];
        int pos = atomicAdd(&g_cursor[dst], 1);
        g_meta[pos] = make_float2(__int_as_float(src), w);
    }
}

// ---------------------------------------------------------------------------
// Gather: one warp per dst node, fp16 rows (256B/row, L2-resident).
// lane covers cols lane*4..lane*4+3; fp32 accumulate; single plain store.
// ---------------------------------------------------------------------------
__global__ __launch_bounds__(256) void gather_kernel(int N) {
    int w = (blockIdx.x * 256 + threadIdx.x) >> 5;
    int lane = threadIdx.x & 31;
    if (w >= N) return;
    int base = g_offs[w];
    int deg = g_count[w];
    float4 acc = make_float4(0.f, 0.f, 0.f, 0.f);

    for (int c0 = 0; c0 < deg; c0 += 32) {
        int cn = min(deg - c0, 32);
        float2 mv = make_float2(0.f, 0.f);
        if (lane < cn) mv = __ldg(&g_meta[base + c0 + lane]);
        for (int j = 0; j < cn; j += 4) {
            uint2 h[4];
            float wv[4];
#pragma unroll
            for (int u = 0; u < 4; ++u) {
                int idx = j + u;
                int su = __shfl_sync(0xffffffffu, __float_as_int(mv.x), idx & 31);
                float wu = __shfl_sync(0xffffffffu, mv.y, idx & 31);
                bool valid = idx < cn;
                wv[u] = valid ? wu : 0.f;
                if (valid)
                    h[u] = __ldg((const uint2*)(g_srcH + (size_t)su * D) + lane);
                else
                    h[u] = make_uint2(0u, 0u);
            }
#pragma unroll
            for (int u = 0; u < 4; ++u) {
                float2 f01 = __half22float2(*(__half2*)&h[u].x);
                float2 f23 = __half22float2(*(__half2*)&h[u].y);
                acc.x += wv[u] * f01.x;
                acc.y += wv[u] * f01.y;
                acc.z += wv[u] * f23.x;
                acc.w += wv[u] * f23.y;
            }
        }
    }
    ((float4*)(g_A + (size_t)w * D))[lane] = acc;
}

// ---------------------------------------------------------------------------
// Fused dual GEMM + leaky_relu on tensor cores (tf32 mma.sync) — R3 verbatim.
//   out = leaky_relu( (dst_x + A) @ Wi^T + (dst_x * A) @ Wn^T )
// ---------------------------------------------------------------------------
#define SSTR 136

__device__ __forceinline__ uint32_t f2tf32(float x) {
    uint32_t r;
    asm("cvt.rna.tf32.f32 %0, %1;" : "=r"(r) : "f"(x));
    return r;
}

__device__ __forceinline__ void mma_tf32(float c[4], const uint32_t a[4],
                                         const uint32_t b[2]) {
    asm volatile(
        "mma.sync.aligned.m16n8k8.row.col.f32.tf32.tf32.f32 "
        "{%0,%1,%2,%3},{%4,%5,%6,%7},{%8,%9},{%0,%1,%2,%3};"
        : "+f"(c[0]), "+f"(c[1]), "+f"(c[2]), "+f"(c[3])
        : "r"(a[0]), "r"(a[1]), "r"(a[2]), "r"(a[3]), "r"(b[0]), "r"(b[1]));
}

__global__ __launch_bounds__(256) void fused_gemm_tc_kernel(
    const float* __restrict__ dstx,
    const float* __restrict__ Wi,
    const float* __restrict__ Wn,
    float* __restrict__ out, int N) {

    __shared__ uint32_t u_s[16][SSTR];
    __shared__ uint32_t v_s[16][SSTR];
    __shared__ uint32_t wi_s[16][SSTR];
    __shared__ uint32_t wn_s[16][SSTR];

    const int tid = threadIdx.x;
    const int lane = tid & 31;
    const int wid = tid >> 5;
    const int wm = wid >> 2;
    const int wn = wid & 3;
    const int grp = lane >> 2;
    const int qid = lane & 3;
    const int row0 = blockIdx.x * 128;

    const int fm = tid >> 1;
    const int fkq = (tid & 1) * 8;

    float acc[4][4][4];
#pragma unroll
    for (int mt = 0; mt < 4; ++mt)
#pragma unroll
        for (int nt = 0; nt < 4; ++nt)
#pragma unroll
            for (int c = 0; c < 4; ++c) acc[mt][nt][c] = 0.f;

    for (int kt = 0; kt < 8; ++kt) {
        const int k0 = kt * 16;
        {
            int row = row0 + fm;
            float4 d0 = make_float4(0.f, 0.f, 0.f, 0.f), d1 = d0;
            float4 a0 = d0, a1 = d0;
            if (row < N) {
                const float4* dp = (const float4*)(dstx + (size_t)row * D + k0 + fkq);
                const float4* ap = (const float4*)(g_A + (size_t)row * D + k0 + fkq);
                d0 = dp[0]; d1 = dp[1];
                a0 = ap[0]; a1 = ap[1];
            }
            float du[8] = {d0.x, d0.y, d0.z, d0.w, d1.x, d1.y, d1.z, d1.w};
            float au[8] = {a0.x, a0.y, a0.z, a0.w, a1.x, a1.y, a1.z, a1.w};
#pragma unroll
            for (int j = 0; j < 8; ++j) {
                u_s[fkq + j][fm] = f2tf32(du[j] + au[j]);
                v_s[fkq + j][fm] = f2tf32(du[j] * au[j]);
            }
            const float4* wip = (const float4*)(Wi + fm * D + k0 + fkq);
            const float4* wnp = (const float4*)(Wn + fm * D + k0 + fkq);
            float4 wi0 = wip[0], wi1 = wip[1];
            float4 wn0 = wnp[0], wn1 = wnp[1];
            float wif[8] = {wi0.x, wi0.y, wi0.z, wi0.w, wi1.x, wi1.y, wi1.z, wi1.w};
            float wnf[8] = {wn0.x, wn0.y, wn0.z, wn0.w, wn1.x, wn1.y, wn1.z, wn1.w};
#pragma unroll
            for (int j = 0; j < 8; ++j) {
                wi_s[fkq + j][fm] = f2tf32(wif[j]);
                wn_s[fkq + j][fm] = f2tf32(wnf[j]);
            }
        }
        __syncthreads();

#pragma unroll
        for (int ph = 0; ph < 2; ++ph) {
            const uint32_t(*S)[SSTR] = ph ? v_s : u_s;
            const uint32_t(*W)[SSTR] = ph ? wn_s : wi_s;
#pragma unroll
            for (int kk = 0; kk < 16; kk += 8) {
                uint32_t af[4][4];
#pragma unroll
                for (int mt = 0; mt < 4; ++mt) {
                    int mr = wm * 64 + mt * 16 + grp;
                    af[mt][0] = S[kk + qid][mr];
                    af[mt][1] = S[kk + qid][mr + 8];
                    af[mt][2] = S[kk + qid + 4][mr];
                    af[mt][3] = S[kk + qid + 4][mr + 8];
                }
                uint32_t bf[4][2];
#pragma unroll
                for (int nt = 0; nt < 4; ++nt) {
                    int nc = wn * 32 + nt * 8 + grp;
                    bf[nt][0] = W[kk + qid][nc];
                    bf[nt][1] = W[kk + qid + 4][nc];
                }
#pragma unroll
                for (int mt = 0; mt < 4; ++mt)
#pragma unroll
                    for (int nt = 0; nt < 4; ++nt)
                        mma_tf32(acc[mt][nt], af[mt], bf[nt]);
            }
        }
        __syncthreads();
    }

#pragma unroll
    for (int mt = 0; mt < 4; ++mt) {
#pragma unroll
        for (int nt = 0; nt < 4; ++nt) {
            int col = wn * 32 + nt * 8 + qid * 2;
            int r0 = row0 + wm * 64 + mt * 16 + grp;
            int r1 = r0 + 8;
            float x0 = acc[mt][nt][0], x1 = acc[mt][nt][1];
            float x2 = acc[mt][nt][2], x3 = acc[mt][nt][3];
            x0 = x0 > 0.f ? x0 : 0.01f * x0;
            x1 = x1 > 0.f ? x1 : 0.01f * x1;
            x2 = x2 > 0.f ? x2 : 0.01f * x2;
            x3 = x3 > 0.f ? x3 : 0.01f * x3;
            if (r0 < N)
                *(float2*)(out + (size_t)r0 * D + col) = make_float2(x0, x1);
            if (r1 < N)
                *(float2*)(out + (size_t)r1 * D + col) = make_float2(x2, x3);
        }
    }
}

// ---------------------------------------------------------------------------
extern "C" void kernel_launch(void* const* d_in, const int* in_sizes, int n_in,
                              void* d_out, int out_size) {
    const float* src_x = (const float*)d_in[0];
    const float* dst_x = (const float*)d_in[1];
    const int*   ei    = (const int*)d_in[2];    // [2, E]
    const float* ew    = (const float*)d_in[3];  // [E]
    const float* Wi    = (const float*)d_in[4];
    const float* Wn    = (const float*)d_in[5];
    float* out = (float*)d_out;

    int N = in_sizes[0] / D;
    int E = in_sizes[2] / 2;
    int nb = (N + 255) / 256;
    int n8 = N * (D / 8);

    convert_kernel<<<(n8 + 255) / 256, 256>>>(src_x, n8);
    zero_count_kernel<<<nb, 256>>>(N);
    hist_kernel<<<(E + 255) / 256, 256>>>(ei, E);
    scan1_kernel<<<nb, 256>>>(N);
    scan2_kernel<<<1, 512>>>(nb);
    scan3_kernel<<<nb, 256>>>(N);
    permute_kernel<<<(E + 255) / 256, 256>>>(ei, ew, E);
    gather_kernel<<<(N * 32 + 255) / 256, 256>>>(N);
    fused_gemm_tc_kernel<<<(N + 127) / 128, 256>>>(dst_x, Wi, Wn, out, N);
}

// round 9
// speedup vs baseline: 1.5398x; 1.0249x over previous
#include <cuda_runtime.h>
#include <cuda_fp16.h>
#include <cstdint>

#define D 128
#define MAXN 100000
#define MAXE 600000
#define SCAN_NB ((MAXN + 255) / 256)   // 391

// Scratch (device globals; no allocs allowed)
__device__ float  g_A[(size_t)MAXN * D];     // 51.2 MB
__device__ __half g_srcH[(size_t)MAXN * D];  // 25.6 MB fp16 src cache
__device__ int    g_count[MAXN];             // zeroed by scan each run (BSS-zero at start)
__device__ int    g_offs[MAXN];
__device__ int    g_state[SCAN_NB];          // lookback state; re-armed by permute
__device__ float2 g_meta[MAXE];              // (.x = src id bits, .y = w)

// ---------------------------------------------------------------------------
// Kernel 0: convert src_x -> fp16 cache  +  histogram of dst (independent jobs)
// ---------------------------------------------------------------------------
__global__ void convert_hist_kernel(const float* __restrict__ src,
                                    const int* __restrict__ ei,
                                    int n8, int E) {
    int i = blockIdx.x * blockDim.x + threadIdx.x;
    if (i < n8) {
        float4 a = __ldg((const float4*)src + 2 * i);
        float4 b = __ldg((const float4*)src + 2 * i + 1);
        __half2 h0 = __floats2half2_rn(a.x, a.y);
        __half2 h1 = __floats2half2_rn(a.z, a.w);
        __half2 h2 = __floats2half2_rn(b.x, b.y);
        __half2 h3 = __floats2half2_rn(b.z, b.w);
        uint4 o;
        o.x = *(uint32_t*)&h0;
        o.y = *(uint32_t*)&h1;
        o.z = *(uint32_t*)&h2;
        o.w = *(uint32_t*)&h3;
        ((uint4*)g_srcH)[i] = o;
    }
    if (i < E) atomicAdd(&g_count[__ldg(&ei[E + i])], 1);
}

// ---------------------------------------------------------------------------
// Kernel 1: single-pass exclusive scan (decoupled lookback, warp-windowed).
// Writes g_offs; zeroes g_count behind itself. State word: (flag<<24)|value,
// flag 0=invalid, 1=aggregate, 2=inclusive prefix. Values <= 600000 < 2^24.
// ---------------------------------------------------------------------------
__global__ __launch_bounds__(256) void scan_kernel(int N) {
    __shared__ int ws[8];
    __shared__ int s_prefix;
    int tid = threadIdx.x, lane = tid & 31, wrp = tid >> 5;
    int b = blockIdx.x;
    int i = b * 256 + tid;
    int c = (i < N) ? g_count[i] : 0;
    if (i < N) g_count[i] = 0;            // restore invariant for next run

    int v = c;
#pragma unroll
    for (int o = 1; o < 32; o <<= 1) {
        int t = __shfl_up_sync(0xffffffffu, v, o);
        if (lane >= o) v += t;
    }
    if (lane == 31) ws[wrp] = v;
    __syncthreads();
    if (wrp == 0) {
        int s = (lane < 8) ? ws[lane] : 0;
#pragma unroll
        for (int o = 1; o < 8; o <<= 1) {
            int t = __shfl_up_sync(0xffffffffu, s, o);
            if (lane >= o) s += t;
        }
        if (lane < 8) ws[lane] = s;
    }
    __syncthreads();
    int incl = v + ((wrp > 0) ? ws[wrp - 1] : 0);
    int total = ws[7];

    if (tid == 0) {
        __threadfence();
        if (b == 0) {
            atomicExch(&g_state[0], (2 << 24) | total);
            s_prefix = 0;
        } else {
            atomicExch(&g_state[b], (1 << 24) | total);
        }
    }

    if (b > 0 && wrp == 0) {
        int agg = 0;
        int p_hi = b - 1;
        while (true) {
            int p = p_hi - lane;
            int st = (p >= 0) ? atomicAdd(&g_state[p], 0) : (2 << 24);
            int flag = st >> 24;
            int val = st & 0xFFFFFF;
            unsigned m2 = __ballot_sync(0xffffffffu, flag == 2);
            unsigned m0 = __ballot_sync(0xffffffffu, flag == 0);
            if (m2) {
                int k = __ffs(m2) - 1;          // lowest lane (= highest p) w/ prefix
                if (m0 & ((1u << k) - 1)) continue;  // unready gap before it: retry
                int vv = (lane <= k) ? val : 0;
#pragma unroll
                for (int o = 16; o; o >>= 1) vv += __shfl_down_sync(0xffffffffu, vv, o);
                vv = __shfl_sync(0xffffffffu, vv, 0);
                agg += vv;
                break;
            } else {
                if (m0) continue;                // some invalid: retry window
                int vv = val;
#pragma unroll
                for (int o = 16; o; o >>= 1) vv += __shfl_down_sync(0xffffffffu, vv, o);
                vv = __shfl_sync(0xffffffffu, vv, 0);
                agg += vv;
                p_hi -= 32;
            }
        }
        if (lane == 0) {
            s_prefix = agg;
            __threadfence();
            atomicExch(&g_state[b], (2 << 24) | (agg + total));
        }
    }
    __syncthreads();
    if (i < N) g_offs[i] = s_prefix + incl - c;   // exclusive prefix
}

// ---------------------------------------------------------------------------
// Kernel 2: permute — write (src,w) into dst-sorted slot, advancing g_offs in
// place. Also re-arms g_state for the next replay (scan has fully completed).
// ---------------------------------------------------------------------------
__global__ void permute_kernel(const int* __restrict__ ei,
                               const float* __restrict__ ew, int E, int nb) {
    int e = blockIdx.x * blockDim.x + threadIdx.x;
    if (e < nb) g_state[e] = 0;
    if (e < E) {
        int dst = ei[E + e];
        int src = ei[e];
        float w = ew[e];
        int pos = atomicAdd(&g_offs[dst], 1);
        g_meta[pos] = make_float2(__int_as_float(src), w);
    }
}

// ---------------------------------------------------------------------------
// Kernel 3 (PROFILED): gather — one warp per dst node, fp16 rows (256B).
// Post-permute identity: offs[w] = orig offs[w+1], so
//   end = offs[w], base = (w>0 ? offs[w-1] : 0), deg = end - base.
// ---------------------------------------------------------------------------
__global__ __launch_bounds__(256) void gather_kernel(int N) {
    int w = (blockIdx.x * 256 + threadIdx.x) >> 5;
    int lane = threadIdx.x & 31;
    if (w >= N) return;
    int end = __ldg(&g_offs[w]);
    int base = (w > 0) ? __ldg(&g_offs[w - 1]) : 0;
    int deg = end - base;
    float4 acc = make_float4(0.f, 0.f, 0.f, 0.f);

    for (int c0 = 0; c0 < deg; c0 += 32) {
        int cn = min(deg - c0, 32);
        float2 mv = make_float2(0.f, 0.f);
        if (lane < cn) mv = __ldg(&g_meta[base + c0 + lane]);
        for (int j = 0; j < cn; j += 4) {
            uint2 h[4];
            float wv[4];
#pragma unroll
            for (int u = 0; u < 4; ++u) {
                int idx = j + u;
                int su = __shfl_sync(0xffffffffu, __float_as_int(mv.x), idx & 31);
                float wu = __shfl_sync(0xffffffffu, mv.y, idx & 31);
                bool valid = idx < cn;
                wv[u] = valid ? wu : 0.f;
                if (valid)
                    h[u] = __ldg((const uint2*)(g_srcH + (size_t)su * D) + lane);
                else
                    h[u] = make_uint2(0u, 0u);
            }
#pragma unroll
            for (int u = 0; u < 4; ++u) {
                float2 f01 = __half22float2(*(__half2*)&h[u].x);
                float2 f23 = __half22float2(*(__half2*)&h[u].y);
                acc.x += wv[u] * f01.x;
                acc.y += wv[u] * f01.y;
                acc.z += wv[u] * f23.x;
                acc.w += wv[u] * f23.y;
            }
        }
    }
    ((float4*)(g_A + (size_t)w * D))[lane] = acc;
}

// ---------------------------------------------------------------------------
// Kernel 4: fused dual GEMM + leaky_relu (tf32 mma.sync) — R3 verbatim.
//   out = leaky_relu( (dst_x + A) @ Wi^T + (dst_x * A) @ Wn^T )
// ---------------------------------------------------------------------------
#define SSTR 136

__device__ __forceinline__ uint32_t f2tf32(float x) {
    uint32_t r;
    asm("cvt.rna.tf32.f32 %0, %1;" : "=r"(r) : "f"(x));
    return r;
}

__device__ __forceinline__ void mma_tf32(float c[4], const uint32_t a[4],
                                         const uint32_t b[2]) {
    asm volatile(
        "mma.sync.aligned.m16n8k8.row.col.f32.tf32.tf32.f32 "
        "{%0,%1,%2,%3},{%4,%5,%6,%7},{%8,%9},{%0,%1,%2,%3};"
        : "+f"(c[0]), "+f"(c[1]), "+f"(c[2]), "+f"(c[3])
        : "r"(a[0]), "r"(a[1]), "r"(a[2]), "r"(a[3]), "r"(b[0]), "r"(b[1]));
}

__global__ __launch_bounds__(256) void fused_gemm_tc_kernel(
    const float* __restrict__ dstx,
    const float* __restrict__ Wi,
    const float* __restrict__ Wn,
    float* __restrict__ out, int N) {

    __shared__ uint32_t u_s[16][SSTR];
    __shared__ uint32_t v_s[16][SSTR];
    __shared__ uint32_t wi_s[16][SSTR];
    __shared__ uint32_t wn_s[16][SSTR];

    const int tid = threadIdx.x;
    const int lane = tid & 31;
    const int wid = tid >> 5;
    const int wm = wid >> 2;
    const int wn = wid & 3;
    const int grp = lane >> 2;
    const int qid = lane & 3;
    const int row0 = blockIdx.x * 128;

    const int fm = tid >> 1;
    const int fkq = (tid & 1) * 8;

    float acc[4][4][4];
#pragma unroll
    for (int mt = 0; mt < 4; ++mt)
#pragma unroll
        for (int nt = 0; nt < 4; ++nt)
#pragma unroll
            for (int c = 0; c < 4; ++c) acc[mt][nt][c] = 0.f;

    for (int kt = 0; kt < 8; ++kt) {
        const int k0 = kt * 16;
        {
            int row = row0 + fm;
            float4 d0 = make_float4(0.f, 0.f, 0.f, 0.f), d1 = d0;
            float4 a0 = d0, a1 = d0;
            if (row < N) {
                const float4* dp = (const float4*)(dstx + (size_t)row * D + k0 + fkq);
                const float4* ap = (const float4*)(g_A + (size_t)row * D + k0 + fkq);
                d0 = dp[0]; d1 = dp[1];
                a0 = ap[0]; a1 = ap[1];
            }
            float du[8] = {d0.x, d0.y, d0.z, d0.w, d1.x, d1.y, d1.z, d1.w};
            float au[8] = {a0.x, a0.y, a0.z, a0.w, a1.x, a1.y, a1.z, a1.w};
#pragma unroll
            for (int j = 0; j < 8; ++j) {
                u_s[fkq + j][fm] = f2tf32(du[j] + au[j]);
                v_s[fkq + j][fm] = f2tf32(du[j] * au[j]);
            }
            const float4* wip = (const float4*)(Wi + fm * D + k0 + fkq);
            const float4* wnp = (const float4*)(Wn + fm * D + k0 + fkq);
            float4 wi0 = wip[0], wi1 = wip[1];
            float4 wn0 = wnp[0], wn1 = wnp[1];
            float wif[8] = {wi0.x, wi0.y, wi0.z, wi0.w, wi1.x, wi1.y, wi1.z, wi1.w};
            float wnf[8] = {wn0.x, wn0.y, wn0.z, wn0.w, wn1.x, wn1.y, wn1.z, wn1.w};
#pragma unroll
            for (int j = 0; j < 8; ++j) {
                wi_s[fkq + j][fm] = f2tf32(wif[j]);
                wn_s[fkq + j][fm] = f2tf32(wnf[j]);
            }
        }
        __syncthreads();

#pragma unroll
        for (int ph = 0; ph < 2; ++ph) {
            const uint32_t(*S)[SSTR] = ph ? v_s : u_s;
            const uint32_t(*W)[SSTR] = ph ? wn_s : wi_s;
#pragma unroll
            for (int kk = 0; kk < 16; kk += 8) {
                uint32_t af[4][4];
#pragma unroll
                for (int mt = 0; mt < 4; ++mt) {
                    int mr = wm * 64 + mt * 16 + grp;
                    af[mt][0] = S[kk + qid][mr];
                    af[mt][1] = S[kk + qid][mr + 8];
                    af[mt][2] = S[kk + qid + 4][mr];
                    af[mt][3] = S[kk + qid + 4][mr + 8];
                }
                uint32_t bf[4][2];
#pragma unroll
                for (int nt = 0; nt < 4; ++nt) {
                    int nc = wn * 32 + nt * 8 + grp;
                    bf[nt][0] = W[kk + qid][nc];
                    bf[nt][1] = W[kk + qid + 4][nc];
                }
#pragma unroll
                for (int mt = 0; mt < 4; ++mt)
#pragma unroll
                    for (int nt = 0; nt < 4; ++nt)
                        mma_tf32(acc[mt][nt], af[mt], bf[nt]);
            }
        }
        __syncthreads();
    }

#pragma unroll
    for (int mt = 0; mt < 4; ++mt) {
#pragma unroll
        for (int nt = 0; nt < 4; ++nt) {
            int col = wn * 32 + nt * 8 + qid * 2;
            int r0 = row0 + wm * 64 + mt * 16 + grp;
            int r1 = r0 + 8;
            float x0 = acc[mt][nt][0], x1 = acc[mt][nt][1];
            float x2 = acc[mt][nt][2], x3 = acc[mt][nt][3];
            x0 = x0 > 0.f ? x0 : 0.01f * x0;
            x1 = x1 > 0.f ? x1 : 0.01f * x1;
            x2 = x2 > 0.f ? x2 : 0.01f * x2;
            x3 = x3 > 0.f ? x3 : 0.01f * x3;
            if (r0 < N)
                *(float2*)(out + (size_t)r0 * D + col) = make_float2(x0, x1);
            if (r1 < N)
                *(float2*)(out + (size_t)r1 * D + col) = make_float2(x2, x3);
        }
    }
}

// ---------------------------------------------------------------------------
extern "C" void kernel_launch(void* const* d_in, const int* in_sizes, int n_in,
                              void* d_out, int out_size) {
    const float* src_x = (const float*)d_in[0];
    const float* dst_x = (const float*)d_in[1];
    const int*   ei    = (const int*)d_in[2];    // [2, E]
    const float* ew    = (const float*)d_in[3];  // [E]
    const float* Wi    = (const float*)d_in[4];
    const float* Wn    = (const float*)d_in[5];
    float* out = (float*)d_out;

    int N = in_sizes[0] / D;
    int E = in_sizes[2] / 2;
    int nb = (N + 255) / 256;
    int n8 = N * (D / 8);
    int gmax = (n8 > E) ? n8 : E;

    convert_hist_kernel<<<(gmax + 255) / 256, 256>>>(src_x, ei, n8, E);
    scan_kernel<<<nb, 256>>>(N);
    permute_kernel<<<(E + 255) / 256, 256>>>(ei, ew, E, nb);
    gather_kernel<<<(N * 32 + 255) / 256, 256>>>(N);
    fused_gemm_tc_kernel<<<(N + 127) / 128, 256>>>(dst_x, Wi, Wn, out, N);
}